// round 6
// baseline (speedup 1.0000x reference)
#include <cuda_runtime.h>
#include <math.h>

#define BB   16
#define NN   96
#define HH   256
#define BINC 11
#define IT   4      // i-rows per block (pair kernel)

// Scratch for y = x @ W_atom  (1.5 MB) — __device__ global, no allocation.
__device__ float g_y[BB * NN * HH];

// ---- packed f32x2 helpers (u64 carrier, "l" constraints) ------------------
typedef unsigned long long f2;
__device__ __forceinline__ f2 pk(float lo, float hi) {
    f2 r; asm("mov.b64 %0, {%1,%2};" : "=l"(r) : "f"(lo), "f"(hi)); return r;
}
__device__ __forceinline__ void upk(f2 v, float& lo, float& hi) {
    asm("mov.b64 {%0,%1}, %2;" : "=f"(lo), "=f"(hi) : "l"(v));
}
__device__ __forceinline__ f2 fma2(f2 a, f2 b, f2 c) {
    f2 d; asm("fma.rn.f32x2 %0, %1, %2, %3;" : "=l"(d) : "l"(a), "l"(b), "l"(c)); return d;
}
__device__ __forceinline__ f2 add2(f2 a, f2 b) {
    f2 d; asm("add.rn.f32x2 %0, %1, %2;" : "=l"(d) : "l"(a), "l"(b)); return d;
}
__device__ __forceinline__ float warp_sum(float v) {
#pragma unroll
    for (int off = 16; off > 0; off >>= 1)
        v += __shfl_xor_sync(0xffffffffu, v, off);
    return v;
}

// ---------------------------------------------------------------------------
// Kernel 1: y = x @ W_atom. Block = 8 rows, 1024 threads = 256 k x 4 h-quarters.
// h-reduction split across thread groups; smem partial reduce.
// Grid 192, 32 warps/block -> ~41 warps/SM: latency fully hidden.
// ---------------------------------------------------------------------------
#define PR 8
__global__ __launch_bounds__(1024) void proj_kernel(const float* __restrict__ x,
                                                    const float* __restrict__ W) {
    __shared__ float xs[PR * HH];              // 8 KB
    __shared__ float part[3][PR * HH];         // 24 KB (quarters 1..3)
    const int r0  = blockIdx.x * PR;
    const int tid = threadIdx.x;
    const int k   = tid & 255;
    const int q   = tid >> 8;                  // h-quarter 0..3

    for (int idx = tid; idx < PR * HH; idx += 1024) xs[idx] = x[r0 * HH + idx];
    __syncthreads();

    f2 acc[PR];
#pragma unroll
    for (int r = 0; r < PR; ++r) acc[r] = 0ull;

    const ulonglong2* xs2 = (const ulonglong2*)xs;   // [r*64 + h4]
    const int h4base = q * 16;
#pragma unroll 4
    for (int h4i = 0; h4i < 16; ++h4i) {
        const int h4 = h4base + h4i;
        const int h  = h4 * 4;
        float w0 = __ldg(&W[(h + 0) * HH + k]);
        float w1 = __ldg(&W[(h + 1) * HH + k]);
        float w2 = __ldg(&W[(h + 2) * HH + k]);
        float w3 = __ldg(&W[(h + 3) * HH + k]);
        f2 wa = pk(w0, w1), wbq = pk(w2, w3);
#pragma unroll
        for (int r = 0; r < PR; ++r) {
            ulonglong2 xv = xs2[r * 64 + h4];
            acc[r] = fma2(xv.x, wa, acc[r]);
            acc[r] = fma2(xv.y, wbq, acc[r]);
        }
    }
    if (q > 0) {
#pragma unroll
        for (int r = 0; r < PR; ++r) {
            float lo, hi; upk(acc[r], lo, hi);
            part[q - 1][r * HH + k] = lo + hi;
        }
    }
    __syncthreads();
    if (q == 0) {
#pragma unroll
        for (int r = 0; r < PR; ++r) {
            float lo, hi; upk(acc[r], lo, hi);
            g_y[(r0 + r) * HH + k] = lo + hi + part[0][r * HH + k]
                                   + part[1][r * HH + k] + part[2][r * HH + k];
        }
    }
}

// ---------------------------------------------------------------------------
// Kernel 2: pair + raw score; sigmoid + context deferred.
// Block = (b, 4 i's). 8 warps = 4 i x 2 H-halves. Warp covers k-half
// [hh*128, hh*128+128): lane owns 4 k (one ulonglong2). Each warp walks all
// 96 j. Half-scores combined in shared; W_bin half-slice in registers (44).
// Target: <=128 regs -> 2 blocks/SM.
// ---------------------------------------------------------------------------
__global__ __launch_bounds__(256, 2) void pair_kernel(
    const float* __restrict__ x,
    const float* __restrict__ bin,
    const float* __restrict__ W_bin,
    const float* __restrict__ b_bin,
    const float* __restrict__ w_score,
    const float* __restrict__ b_score,
    float* __restrict__ ctx_out,
    float* __restrict__ pair_out)
{
    const int blk = blockIdx.x;
    const int b   = blk / (NN / IT);
    const int i0  = (blk % (NN / IT)) * IT;
    const int tid = threadIdx.x;
    const int w   = tid >> 5;
    const int L   = tid & 31;
    const int iw  = w & 3;
    const int hh  = w >> 2;                  // H-half 0/1
    const int kq  = hh * 32 + L;             // ulonglong2 index in a 256-f row
    const int bi  = b * NN + i0 + iw;

    __shared__ __align__(16) float sbin[IT * NN * 12];   // repacked bin rows (18.4 KB)
    __shared__ float att_h[2][IT][NN];                   // half raw scores (3 KB)

    // ---- stage bin slice (contiguous source, repack 11 -> 12 stride) ----
    {
        const float* src = bin + (size_t)(b * NN + i0) * NN * BINC;
        for (int idx = tid; idx < IT * NN * BINC; idx += 256) {
            const int row = idx / BINC;
            const int c   = idx - row * BINC;
            sbin[row * 12 + c] = src[idx];
        }
    }

    // ---- register-resident half-slices ----
    f2 wb[BINC][2];
#pragma unroll
    for (int c = 0; c < BINC; ++c) {
        ulonglong2 a = ((const ulonglong2*)(W_bin + c * HH))[kq];
        wb[c][0] = a.x; wb[c][1] = a.y;
    }
    f2 ws0, ws1;
    { ulonglong2 a = ((const ulonglong2*)w_score)[kq]; ws0 = a.x; ws1 = a.y; }
    f2 base0, base1, xi0, xi1;
    {
        ulonglong2 yv = ((const ulonglong2*)(g_y + bi * HH))[kq];
        ulonglong2 bv = ((const ulonglong2*)b_bin)[kq];
        ulonglong2 xv = ((const ulonglong2*)(x + bi * HH))[kq];
        base0 = add2(yv.x, bv.x); base1 = add2(yv.y, bv.y);
        xi0 = xv.x; xi1 = xv.y;
    }

    const ulonglong2* ybase = (const ulonglong2*)(g_y + b * NN * HH);
    const ulonglong2* xbase = (const ulonglong2*)(x   + b * NN * HH);
    ulonglong2*       pob   = (ulonglong2*)(pair_out + (size_t)bi * NN * HH);
    const float4*     sbp   = (const float4*)(sbin + iw * NN * 12);
    __syncthreads();   // sbin staged

    // preload j = 0
    ulonglong2 yj = ybase[kq];
    ulonglong2 xj = xbase[kq];

    for (int j = 0; j < NN; ++j) {
        // bin coeffs for this j: 3x LDS.128 (broadcast, conflict-free)
        const float4 c0 = sbp[j * 3 + 0];
        const float4 c1 = sbp[j * 3 + 1];
        const float4 c2 = sbp[j * 3 + 2];

        f2 h0 = add2(base0, yj.x), h1 = add2(base1, yj.y);
        f2 p0 = add2(xi0,  xj.x),  p1 = add2(xi1,  xj.y);
        pob[j * 64 + kq] = make_ulonglong2(p0, p1);

        // prefetch next j (buffers dead)
        const int jn = (j < NN - 1) ? j + 1 : j;
        yj = ybase[jn * 64 + kq];
        xj = xbase[jn * 64 + kq];

        // bin projection: 22 packed FMAs from registers
        float bc[BINC] = {c0.x, c0.y, c0.z, c0.w, c1.x, c1.y, c1.z, c1.w,
                          c2.x, c2.y, c2.z};
#pragma unroll
        for (int c = 0; c < BINC; ++c) {
            f2 s = pk(bc[c], bc[c]);
            h0 = fma2(s, wb[c][0], h0);
            h1 = fma2(s, wb[c][1], h1);
        }

        // relu + score dot over this half
        float a0, a1, a2, a3;
        upk(h0, a0, a1); upk(h1, a2, a3);
        a0 = fmaxf(a0, 0.f); a1 = fmaxf(a1, 0.f);
        a2 = fmaxf(a2, 0.f); a3 = fmaxf(a3, 0.f);
        f2 q0 = pk(a0, a1), q1 = pk(a2, a3);
        f2 d  = fma2(q0, ws0, fma2(q1, ws1, 0ull));
        float dl, dh; upk(d, dl, dh);
        const float s = warp_sum(dl + dh);
        if (L == 0) att_h[hh][iw][j] = s;
    }
    __syncthreads();

    // ---- combine halves + sigmoid (in place into att_h[0]) ----
    const float bsc = __ldg(b_score);
    float* a0p = &att_h[0][0][0];
    const float* a1p = &att_h[1][0][0];
    for (int idx = tid; idx < IT * NN; idx += 256)
        a0p[idx] = 1.f / (1.f + __expf(-(a0p[idx] + a1p[idx] + bsc)));
    __syncthreads();

    // ---- context epilogue: ctx[i,k] = sum_j att[i][j] * x[b,j,k] ----
    const float* xrow = x + (size_t)b * NN * HH + tid;   // thread owns k = tid
    float c0 = 0.f, c1 = 0.f, c2 = 0.f, c3 = 0.f;
#pragma unroll 4
    for (int jj = 0; jj < NN; ++jj) {
        const float xv = xrow[jj * HH];
        c0 = fmaf(att_h[0][0][jj], xv, c0);
        c1 = fmaf(att_h[0][1][jj], xv, c1);
        c2 = fmaf(att_h[0][2][jj], xv, c2);
        c3 = fmaf(att_h[0][3][jj], xv, c3);
    }
    float* co = ctx_out + (size_t)(b * NN + i0) * HH + tid;
    co[0 * HH] = c0; co[1 * HH] = c1; co[2 * HH] = c2; co[3 * HH] = c3;
}

// ---------------------------------------------------------------------------
extern "C" void kernel_launch(void* const* d_in, const int* in_sizes, int n_in,
                              void* d_out, int out_size) {
    const float* x       = (const float*)d_in[0];
    const float* bin     = (const float*)d_in[1];
    const float* W_atom  = (const float*)d_in[2];
    const float* W_bin   = (const float*)d_in[3];
    const float* b_bin   = (const float*)d_in[4];
    const float* w_score = (const float*)d_in[5];
    const float* b_score = (const float*)d_in[6];

    float* out  = (float*)d_out;
    float* ctx  = out;                            // context: B*N*H
    float* pair = out + (size_t)BB * NN * HH;     // atom_pair: B*N*N*H

    proj_kernel<<<BB * NN / PR, 1024>>>(x, W_atom);
    pair_kernel<<<BB * NN / IT, 256>>>(x, bin, W_bin, b_bin, w_score, b_score, ctx, pair);
}

// round 7
// speedup vs baseline: 1.1997x; 1.1997x over previous
#include <cuda_runtime.h>
#include <math.h>

#define BB   16
#define NN   96
#define HH   256
#define BINC 11

// Scratch (__device__ globals: no allocation).
__device__ float g_yb [BB * NN * HH];   // y + b_bin   (base rows, 1.5 MB)
__device__ float g_yT [BB * HH * NN];   // y transposed [b][k][j] (1.5 MB)
__device__ float g_att[BB * NN * NN];   // sigmoided scores (0.6 MB)

// ---- packed f32x2 helpers (u64 carrier, "l" constraints) ------------------
typedef unsigned long long f2;
__device__ __forceinline__ f2 pk(float lo, float hi) {
    f2 r; asm("mov.b64 %0, {%1,%2};" : "=l"(r) : "f"(lo), "f"(hi)); return r;
}
__device__ __forceinline__ void upk(f2 v, float& lo, float& hi) {
    asm("mov.b64 {%0,%1}, %2;" : "=f"(lo), "=f"(hi) : "l"(v));
}
__device__ __forceinline__ f2 fma2(f2 a, f2 b, f2 c) {
    f2 d; asm("fma.rn.f32x2 %0, %1, %2, %3;" : "=l"(d) : "l"(a), "l"(b), "l"(c)); return d;
}
__device__ __forceinline__ f2 add2(f2 a, f2 b) {
    f2 d; asm("add.rn.f32x2 %0, %1, %2;" : "=l"(d) : "l"(a), "l"(b)); return d;
}

// ---------------------------------------------------------------------------
// Kernel 1: y = x @ W_atom. Block = 8 rows, 1024 threads = 256 k x 4 h-quarters.
// Writes g_yb = y + b_bin (coalesced) and g_yT (transposed, strided).
// ---------------------------------------------------------------------------
#define PR 8
__global__ __launch_bounds__(1024) void proj_kernel(const float* __restrict__ x,
                                                    const float* __restrict__ W,
                                                    const float* __restrict__ b_bin) {
    __shared__ float xs[PR * HH];              // 8 KB
    __shared__ float part[3][PR * HH];         // 24 KB (quarters 1..3)
    const int r0  = blockIdx.x * PR;           // 8 rows, same batch (96 % 8 == 0)
    const int tid = threadIdx.x;
    const int k   = tid & 255;
    const int q   = tid >> 8;                  // h-quarter 0..3
    const int b   = r0 / NN;
    const int jl  = r0 % NN;

    for (int idx = tid; idx < PR * HH; idx += 1024) xs[idx] = x[r0 * HH + idx];
    __syncthreads();

    f2 acc[PR];
#pragma unroll
    for (int r = 0; r < PR; ++r) acc[r] = 0ull;

    const ulonglong2* xs2 = (const ulonglong2*)xs;   // [r*64 + h4]
    const int h4base = q * 16;
#pragma unroll 4
    for (int h4i = 0; h4i < 16; ++h4i) {
        const int h4 = h4base + h4i;
        const int h  = h4 * 4;
        float w0 = __ldg(&W[(h + 0) * HH + k]);
        float w1 = __ldg(&W[(h + 1) * HH + k]);
        float w2 = __ldg(&W[(h + 2) * HH + k]);
        float w3 = __ldg(&W[(h + 3) * HH + k]);
        f2 wa = pk(w0, w1), wbq = pk(w2, w3);
#pragma unroll
        for (int r = 0; r < PR; ++r) {
            ulonglong2 xv = xs2[r * 64 + h4];
            acc[r] = fma2(xv.x, wa, acc[r]);
            acc[r] = fma2(xv.y, wbq, acc[r]);
        }
    }
    if (q > 0) {
#pragma unroll
        for (int r = 0; r < PR; ++r) {
            float lo, hi; upk(acc[r], lo, hi);
            part[q - 1][r * HH + k] = lo + hi;
        }
    }
    __syncthreads();
    if (q == 0) {
        const float bbk = __ldg(&b_bin[k]);
#pragma unroll
        for (int r = 0; r < PR; ++r) {
            float lo, hi; upk(acc[r], lo, hi);
            const float v = lo + hi + part[0][r * HH + k]
                          + part[1][r * HH + k] + part[2][r * HH + k];
            g_yb[(r0 + r) * HH + k]        = v + bbk;
            g_yT[(b * HH + k) * NN + jl + r] = v;
        }
    }
}

// ---------------------------------------------------------------------------
// Kernel 2: scores. Block = (b, 4 i) x 3 j-groups = 12 warps, 384 threads.
// Thread owns one (i, j): loops k, NO cross-lane reduction, NO shuffles.
// Per 4k: 13 LDS.128 broadcast + 4 coalesced LDG(yT) + 26 packed FMAs.
// ---------------------------------------------------------------------------
__global__ __launch_bounds__(384, 2) void score_kernel(
    const float* __restrict__ bin,
    const float* __restrict__ W_bin,
    const float* __restrict__ w_score,
    const float* __restrict__ b_score)
{
    __shared__ float Wb_s[BINC * HH];      // 11 KB
    __shared__ float ws_s[HH];             // 1 KB
    __shared__ float yb_s[4 * HH];         // 4 KB  (base rows for the 4 i's)
    __shared__ float sbin[4 * NN * BINC];  // 16.5 KB

    const int blk = blockIdx.x;            // 0..383
    const int b   = blk / (NN / 4);
    const int i0  = (blk % (NN / 4)) * 4;
    const int tid = threadIdx.x;
    const int w   = tid >> 5;
    const int L   = tid & 31;
    const int iw  = w & 3;                  // i within block
    const int jg  = w >> 2;                 // j-group 0..2
    const int i   = i0 + iw;
    const int j   = jg * 32 + L;

    // ---- stage all operands (coalesced) ----
    for (int idx = tid; idx < BINC * HH; idx += 384) Wb_s[idx] = W_bin[idx];
    for (int idx = tid; idx < HH; idx += 384)        ws_s[idx] = w_score[idx];
    for (int idx = tid; idx < 4 * HH; idx += 384)
        yb_s[idx] = g_yb[(b * NN + i0) * HH + idx];
    {
        const float* src = bin + (size_t)(b * NN + i0) * NN * BINC;
        for (int idx = tid; idx < 4 * NN * BINC; idx += 384) sbin[idx] = src[idx];
    }
    __syncthreads();

    // bin coeffs for this (i,j): 11 LDS, stride 11 (coprime to 32 -> conflict-free)
    f2 bc2[BINC];
#pragma unroll
    for (int c = 0; c < BINC; ++c) {
        const float v = sbin[(iw * NN + j) * BINC + c];
        bc2[c] = pk(v, v);
    }

    const float* yTp = g_yT + (size_t)b * HH * NN + j;   // [k]: +k*NN
    const ulonglong2* wbp = (const ulonglong2*)Wb_s;     // [c*64 + k4]
    const ulonglong2* bsp = (const ulonglong2*)(yb_s + iw * HH);
    const ulonglong2* wsp = (const ulonglong2*)ws_s;

    f2 acc2 = 0ull;
    for (int k4 = 0; k4 < HH / 4; ++k4) {
        const int k = k4 * 4;
        // y_j for 4 consecutive k (coalesced across lanes, L2-resident)
        const float y0 = yTp[(k + 0) * NN];
        const float y1 = yTp[(k + 1) * NN];
        const float y2 = yTp[(k + 2) * NN];
        const float y3 = yTp[(k + 3) * NN];

        ulonglong2 bs = bsp[k4];           // base (y_i + b_bin), packed pairs
        f2 h01 = add2(bs.x, pk(y0, y1));
        f2 h23 = add2(bs.y, pk(y2, y3));

#pragma unroll
        for (int c = 0; c < BINC; ++c) {
            ulonglong2 wv = wbp[c * 64 + k4];
            h01 = fma2(bc2[c], wv.x, h01);
            h23 = fma2(bc2[c], wv.y, h23);
        }

        float a0, a1, a2, a3;
        upk(h01, a0, a1); upk(h23, a2, a3);
        a0 = fmaxf(a0, 0.f); a1 = fmaxf(a1, 0.f);
        a2 = fmaxf(a2, 0.f); a3 = fmaxf(a3, 0.f);

        ulonglong2 wsv = wsp[k4];
        acc2 = fma2(pk(a0, a1), wsv.x, acc2);
        acc2 = fma2(pk(a2, a3), wsv.y, acc2);
    }

    float sl, sh; upk(acc2, sl, sh);
    const float s = sl + sh + __ldg(b_score);
    g_att[(size_t)(b * NN + i) * NN + j] = 1.f / (1.f + __expf(-s));
}

// ---------------------------------------------------------------------------
// Kernel 3: streaming writer. Block = (b,i). pair[i,j,k] = x_i[k]+x_j[k]
// via float4 __stcs (evict-first). Context fused from staged att.
// ---------------------------------------------------------------------------
__global__ __launch_bounds__(256) void writer_kernel(
    const float* __restrict__ x,
    float* __restrict__ ctx_out,
    float* __restrict__ pair_out)
{
    const int blk = blockIdx.x;            // b*NN + i
    const int b   = blk / NN;
    const int tid = threadIdx.x;
    const int tq  = tid & 63;              // k-quad 0..63
    const int ph  = tid >> 6;              // j-phase 0..3

    __shared__ float att_sh[NN];
    __shared__ float cpart[4][HH];

    const float4* x4 = (const float4*)(x + (size_t)b * NN * HH);   // [j*64 + q]
    const float4 xi4 = x4[(blk % NN) * 64 + tq];
    if (tid < NN) att_sh[tid] = g_att[(size_t)blk * NN + tid];
    __syncthreads();

    float4* po = (float4*)(pair_out + (size_t)blk * NN * HH);
    float c0 = 0.f, c1 = 0.f, c2 = 0.f, c3 = 0.f;
#pragma unroll 4
    for (int jj = 0; jj < NN / 4; ++jj) {
        const int j = ph + 4 * jj;
        const float4 xj = x4[j * 64 + tq];
        const float  a  = att_sh[j];
        __stcs(&po[j * 64 + tq], make_float4(xi4.x + xj.x, xi4.y + xj.y,
                                             xi4.z + xj.z, xi4.w + xj.w));
        c0 = fmaf(a, xj.x, c0); c1 = fmaf(a, xj.y, c1);
        c2 = fmaf(a, xj.z, c2); c3 = fmaf(a, xj.w, c3);
    }
    ((float4*)cpart[ph])[tq] = make_float4(c0, c1, c2, c3);
    __syncthreads();

    const int k = tid;
    ctx_out[(size_t)blk * HH + k] =
        cpart[0][k] + cpart[1][k] + cpart[2][k] + cpart[3][k];
}

// ---------------------------------------------------------------------------
extern "C" void kernel_launch(void* const* d_in, const int* in_sizes, int n_in,
                              void* d_out, int out_size) {
    const float* x       = (const float*)d_in[0];
    const float* bin     = (const float*)d_in[1];
    const float* W_atom  = (const float*)d_in[2];
    const float* W_bin   = (const float*)d_in[3];
    const float* b_bin   = (const float*)d_in[4];
    const float* w_score = (const float*)d_in[5];
    const float* b_score = (const float*)d_in[6];

    float* out  = (float*)d_out;
    float* ctx  = out;                            // context: B*N*H
    float* pair = out + (size_t)BB * NN * HH;     // atom_pair: B*N*N*H

    proj_kernel  <<<BB * NN / PR, 1024>>>(x, W_atom, b_bin);
    score_kernel <<<BB * NN / 4, 384>>>(bin, W_bin, w_score, b_score);
    writer_kernel<<<BB * NN, 256>>>(x, ctx, pair);
}